// round 3
// baseline (speedup 1.0000x reference)
#include <cuda_runtime.h>
#include <cstdint>

// Problem constants
#define N_B 4
#define C_  32
#define L_  8
#define D_  24
#define H_  24
#define W_  24
#define PLANE (H_*W_)          // 576

// smem x tile: 32 ci x 26 x 26 halo plane, row stride padded to 29
#define XS_WS 29
#define XS_HN 26
#define XS_CI (XS_HN*XS_WS)    // 754
#define XS_SIZE (32*XS_CI)     // 24128 floats
#define WS_SIZE (32*9*32)      // 9216 floats: [ci][tap][co]
#define SMEM_BYTES ((XS_SIZE + WS_SIZE)*4)   // 133376 B

// Reordered weights: [kl][kd][ci][tap(kh*3+kw)][co]
__device__ float g_wre[3*3*32*9*32];   // 82944 floats

__global__ void prep_w_kernel(const float* __restrict__ w) {
    int o = blockIdx.x * 256 + threadIdx.x;
    if (o >= 82944) return;
    int co = o & 31;
    int t  = (o >> 5) % 9;
    int ci = (o / 288) & 31;
    int kd = (o / 9216) % 3;
    int kl = o / 27648;
    // src layout: (ci, co, kl, kd, kh, kw), kh*3+kw == t
    g_wre[o] = w[(ci*32 + co)*81 + kl*27 + kd*9 + t];
}

// ---- Blackwell packed fp32x2 helpers ----
__device__ __forceinline__ void ffma2(uint64_t& d, uint64_t a, uint64_t b) {
    asm("fma.rn.f32x2 %0, %1, %2, %0;" : "+l"(d) : "l"(a), "l"(b));
}
__device__ __forceinline__ uint64_t pack_dup(float v) {
    uint64_t r;
    asm("mov.b64 %0, {%1, %1};" : "=l"(r) : "f"(v));
    return r;
}
__device__ __forceinline__ float2 unpack2(uint64_t v) {
    float2 r;
    asm("mov.b64 {%0, %1}, %2;" : "=f"(r.x), "=f"(r.y) : "l"(v));
    return r;
}

__global__ void __launch_bounds__(576, 1)
convt4d_kernel(const float* __restrict__ x,
               const float* __restrict__ bias,
               float* __restrict__ out)
{
    extern __shared__ float smem[];
    float* xs = smem;
    float* ws = smem + XS_SIZE;

    const int od = blockIdx.x, ol = blockIdx.y, n = blockIdx.z;
    const int tid = threadIdx.x;
    const int co_base = (tid / 144) * 8;   // 4 groups of 8 output channels
    const int s = tid % 144;               // 24 rows x 6 strips
    const int oh = s / 6;
    const int wbase = (s % 6) * 4;         // 4-wide output strip

    // acc[c*4+p]: co-pair c (channels co_base+2c, +2c+1) at spatial offset p
    uint64_t acc[16];
#pragma unroll
    for (int i = 0; i < 16; i++) acc[i] = 0ull;

    const int l0 = ol > 0 ? ol - 1 : 0;
    const int l1 = ol < L_-1 ? ol + 1 : L_-1;
    const int d0 = od > 0 ? od - 1 : 0;
    const int d1 = od < D_-1 ? od + 1 : D_-1;

    for (int lp = l0; lp <= l1; lp++) {
        const int kl = ol + 1 - lp;
        for (int dp = d0; dp <= d1; dp++) {
            const int kd = od + 1 - dp;
            __syncthreads();   // protect smem from previous iteration's readers

            // ---- stage x plane (n, :, lp, dp, :, :) with halo into smem ----
            const size_t base0 = ((size_t)((n*32)*8 + lp)*24 + dp) * (size_t)PLANE;
            for (int idx = tid; idx < 32*26*26; idx += 576) {
                int ci = idx / 676;
                int r  = idx - ci*676;
                int hh = r / 26;
                int ww = r - hh*26;
                int hp = hh - 1, wp = ww - 1;
                float v = 0.f;
                if ((unsigned)hp < 24u && (unsigned)wp < 24u)
                    v = x[base0 + (size_t)ci*110592 + hp*24 + wp];
                xs[ci*XS_CI + hh*XS_WS + ww] = v;
            }
            // ---- stage weight slab for (kl, kd): [ci][tap][co], contiguous ----
            const float* wsrc = g_wre + (kl*3 + kd)*9216;
            for (int i = tid; i < 9216; i += 576) ws[i] = wsrc[i];
            __syncthreads();

            // ---- compute: packed f32x2 over co-pairs ----
#pragma unroll 1
            for (int ci = 0; ci < 32; ci++) {
                const float* xci = xs + ci*XS_CI;
                const float* wci = ws + ci*288 + co_base;
#pragma unroll
                for (int kh = 0; kh < 3; kh++) {
                    const float* xrow0 = xci + (oh + 2 - kh)*XS_WS + wbase;
                    uint64_t xd[6];
#pragma unroll
                    for (int j = 0; j < 6; j++) xd[j] = pack_dup(xrow0[j]);
#pragma unroll
                    for (int kw = 0; kw < 3; kw++) {
                        // two LDS.128 -> four packed co-pair weights
                        const ulonglong2* wp2 =
                            (const ulonglong2*)(wci + (kh*3 + kw)*32);
                        ulonglong2 wA = wp2[0];
                        ulonglong2 wB = wp2[1];
                        uint64_t wv[4] = {wA.x, wA.y, wB.x, wB.y};
#pragma unroll
                        for (int c = 0; c < 4; c++) {
#pragma unroll
                            for (int p = 0; p < 4; p++)
                                ffma2(acc[c*4 + p], wv[c], xd[p + 2 - kw]);
                        }
                    }
                }
            }
        }
    }

    // ---- bias + unpack + vectorized store ----
#pragma unroll
    for (int c = 0; c < 4; c++) {
        const int co0 = co_base + 2*c;
        const float b0 = __ldg(bias + co0);
        const float b1 = __ldg(bias + co0 + 1);
        float4 v0, v1;
        float2 t;
        t = unpack2(acc[c*4 + 0]); v0.x = t.x + b0; v1.x = t.y + b1;
        t = unpack2(acc[c*4 + 1]); v0.y = t.x + b0; v1.y = t.y + b1;
        t = unpack2(acc[c*4 + 2]); v0.z = t.x + b0; v1.z = t.y + b1;
        t = unpack2(acc[c*4 + 3]); v0.w = t.x + b0; v1.w = t.y + b1;
        const size_t o0 = ((size_t)((n*32 + co0)*8 + ol)*24 + od)*PLANE
                          + oh*24 + wbase;
        *(float4*)(out + o0)          = v0;
        *(float4*)(out + o0 + (size_t)8*24*PLANE) = v1;   // next channel
    }
}

extern "C" void kernel_launch(void* const* d_in, const int* in_sizes, int n_in,
                              void* d_out, int out_size) {
    const float* x    = (const float*)d_in[0];
    const float* w    = (const float*)d_in[1];
    const float* bias = (const float*)d_in[2];
    float* out = (float*)d_out;

    cudaFuncSetAttribute(convt4d_kernel,
                         cudaFuncAttributeMaxDynamicSharedMemorySize, SMEM_BYTES);

    prep_w_kernel<<<324, 256>>>(w);          // 324*256 == 82944 exactly

    dim3 grid(D_, L_, N_B);                  // (od, ol, n)
    convt4d_kernel<<<grid, 576, SMEM_BYTES>>>(x, bias, out);
}

// round 5
// speedup vs baseline: 1.9599x; 1.9599x over previous
#include <cuda_runtime.h>
#include <cstdint>

// ---------------- problem constants ----------------
#define L_ 8
#define D_ 24
#define THREADS 384

// ---------------- smem layout ----------------
#define CISTR 707                    // ci stride in words (coprime with 32 banks)
#define XS_WORDS (32*CISTR)          // 22624 words
#define XS_BYTES (XS_WORDS*4)        // 90496 B
#define BS_WORDS 9216                // one (kl,kd) slab, fragment-packed
#define BIAS_OFF (XS_BYTES + BS_WORDS*4)     // 127360
#define SMEM_BYTES (BIAS_OFF + 128)          // 127488

__device__ __forceinline__ uint32_t tf32r(float f) {
    uint32_t b;
    asm("cvt.rna.tf32.f32 %0, %1;" : "=r"(b) : "f"(f));
    return b;
}

__device__ __forceinline__ void mma_tf32(float* d, const uint32_t* a, uint2 b) {
    asm volatile(
        "mma.sync.aligned.m16n8k8.row.col.f32.tf32.tf32.f32 "
        "{%0,%1,%2,%3}, {%4,%5,%6,%7}, {%8,%9}, {%0,%1,%2,%3};"
        : "+f"(d[0]), "+f"(d[1]), "+f"(d[2]), "+f"(d[3])
        : "r"(a[0]), "r"(a[1]), "r"(a[2]), "r"(a[3]), "r"(b.x), "r"(b.y));
}

// Weights pre-packed in mma B-fragment order, tf32-rounded.
// [slab(kl*3+kd)][ks(t*4+kc)][nt][lane][2]  => 9*36*4*64 = 82944 words
__device__ uint32_t g_w2[82944];

__global__ void prep_w(const float* __restrict__ w) {
    int o = blockIdx.x * 256 + threadIdx.x;
    if (o >= 82944) return;
    int pair = o & 1;
    int lane = (o >> 1) & 31;
    int nt   = (o >> 6) & 3;
    int ks   = (o >> 8) % 36;
    int slab = o / 9216;
    int tig = lane & 3, gc = lane >> 2;
    int t = ks >> 2, kc = ks & 3;
    int ci = kc * 8 + tig + pair * 4;    // b0: k=tig, b1: k=tig+4
    int co = nt * 8 + gc;
    int kh = t / 3, kw = t % 3;
    int kl = slab / 3, kd = slab % 3;
    g_w2[o] = tf32r(w[(ci * 32 + co) * 81 + kl * 27 + kd * 9 + kh * 3 + kw]);
}

__global__ void __launch_bounds__(THREADS, 1)
conv_mma(const float* __restrict__ x, const float* __restrict__ bias,
         float* __restrict__ out)
{
    extern __shared__ char smem[];
    uint32_t* xs = (uint32_t*)smem;             // [ci][26 x 27 halo plane], stride CISTR
    uint32_t* bs = xs + XS_WORDS;               // fragment-packed B slab
    float* bsm   = (float*)(smem + BIAS_OFF);   // bias

    const int tid  = threadIdx.x;
    const int wid  = tid >> 5;
    const int lane = tid & 31;
    const int gr   = lane >> 2;   // groupID
    const int tig  = lane & 3;    // threadID_in_group

    if (tid < 32) bsm[tid] = bias[tid];
    // zero whole xs once: halo stays zero, interior overwritten per slab
    for (int i = tid; i < XS_WORDS; i += THREADS) xs[i] = 0u;

    const int od = blockIdx.x, ol = blockIdx.y, n = blockIdx.z;
    const int l0 = ol > 0 ? ol - 1 : 0;
    const int l1 = ol < L_ - 1 ? ol + 1 : L_ - 1;
    const int d0 = od > 0 ? od - 1 : 0;
    const int d1 = od < D_ - 1 ? od + 1 : D_ - 1;

    // 3 M-tiles of 16 rows per warp; per-thread row bases in halo coords
    int mb[3], q0b[3], q1b[3];
#pragma unroll
    for (int j = 0; j < 3; j++) {
        mb[j] = (wid * 3 + j) * 16;
        int r0 = mb[j] + gr, r1 = r0 + 8;
        q0b[j] = (r0 / 24) * 27 + (r0 % 24);
        q1b[j] = (r1 / 24) * 27 + (r1 % 24);
    }
    // tap offset: (2-kh)*27 + (2-kw)
    const int dtap[9] = {56, 55, 54, 29, 28, 27, 2, 1, 0};

    float d[48];   // [mtile 3][ntile 4][4]
#pragma unroll
    for (int i = 0; i < 48; i++) d[i] = 0.f;

    for (int lp = l0; lp <= l1; lp++) {
        const int kl = ol + 1 - lp;
        for (int dp = d0; dp <= d1; dp++) {
            const int kd = od + 1 - dp;
            __syncthreads();   // previous compute done before overwriting smem

            // ---- stage x plane (tf32-rounded) into haloed xs ----
            const float* xsrc = x + (((size_t)(n * 32) * 8 + lp) * 24 + dp) * 576;
            for (int idx = tid; idx < 32 * 576; idx += THREADS) {
                int ci = idx / 576;
                int p  = idx - ci * 576;
                int ih = p / 24, iw = p - ih * 24;
                xs[ci * CISTR + (ih + 1) * 27 + (iw + 1)] =
                    tf32r(xsrc[(size_t)ci * 110592 + p]);
            }
            // ---- stage fragment-packed B slab ----
            {
                const float4* src = (const float4*)(g_w2 + (kl * 3 + kd) * 9216);
                float4* dst = (float4*)bs;
                for (int i = tid; i < 2304; i += THREADS) dst[i] = src[i];
            }
            __syncthreads();

            // ---- compute: 9 taps x 4 k-chunks x (3 mtiles x 4 ntiles) mma ----
#pragma unroll 1
            for (int t = 0; t < 9; t++) {
                const int dt = dtap[t];
                int q0[3], q1[3];
#pragma unroll
                for (int j = 0; j < 3; j++) { q0[j] = q0b[j] + dt; q1[j] = q1b[j] + dt; }
#pragma unroll
                for (int kc = 0; kc < 4; kc++) {
                    const int cib = (kc * 8 + tig) * CISTR;
                    uint32_t a[3][4];
#pragma unroll
                    for (int j = 0; j < 3; j++) {
                        a[j][0] = xs[cib + q0[j]];
                        a[j][1] = xs[cib + q1[j]];
                        a[j][2] = xs[cib + 4 * CISTR + q0[j]];
                        a[j][3] = xs[cib + 4 * CISTR + q1[j]];
                    }
                    const int ksb = (t * 4 + kc) * 4;
#pragma unroll
                    for (int nt = 0; nt < 4; nt++) {
                        uint2 b = *(const uint2*)&bs[(ksb + nt) * 64 + lane * 2];
#pragma unroll
                        for (int j = 0; j < 3; j++)
                            mma_tf32(d + (j * 4 + nt) * 4, a[j], b);
                    }
                }
            }
        }
    }

    // ---- epilogue: bias + store ----
    const size_t ob = (((size_t)(n * 32) * 8 + ol) * 24 + od) * 576;
#pragma unroll
    for (int j = 0; j < 3; j++) {
        const int m0 = mb[j] + gr, m1 = m0 + 8;
#pragma unroll
        for (int nt = 0; nt < 4; nt++) {
            const int co0 = nt * 8 + tig * 2;
            const float b0 = bsm[co0], b1 = bsm[co0 + 1];
            const float* dd = d + (j * 4 + nt) * 4;
            float* o0 = out + ob + (size_t)co0 * 110592;
            float* o1 = o0 + 110592;
            o0[m0] = dd[0] + b0;
            o1[m0] = dd[1] + b1;
            o0[m1] = dd[2] + b0;
            o1[m1] = dd[3] + b1;
        }
    }
}

extern "C" void kernel_launch(void* const* d_in, const int* in_sizes, int n_in,
                              void* d_out, int out_size) {
    const float* x    = (const float*)d_in[0];
    const float* w    = (const float*)d_in[1];
    const float* bias = (const float*)d_in[2];
    float* out = (float*)d_out;

    cudaFuncSetAttribute(conv_mma,
                         cudaFuncAttributeMaxDynamicSharedMemorySize, SMEM_BYTES);

    prep_w<<<324, 256>>>(w);                 // 324*256 == 82944

    dim3 grid(24, L_, 4);                    // (od, ol, n)
    conv_mma<<<grid, THREADS, SMEM_BYTES>>>(x, bias, out);
}

// round 6
// speedup vs baseline: 4.7619x; 2.4297x over previous
#include <cuda_runtime.h>
#include <cuda_fp16.h>
#include <cstdint>

// ---------------- problem constants ----------------
#define L_ 8
#define D_ 24
#define THREADS 288

// ---------------- smem layout ----------------
// xs: 378 halo rows (14 hh x 27 ww) x 36 fp16 (32 ci + pad)
#define XROW 36
#define XS_HALFS (378*XROW)              // 13608
#define XS_BYTES (XS_HALFS*2)            // 27216
#define BS_OFF   XS_BYTES                // fragment-packed B slab (u32 words)
#define BS_WORDS 4608                    // 18 ks x 4 nt x 64
#define BIAS_OFF (BS_OFF + BS_WORDS*4)   // 45648
#define SMEM_BYTES (BIAS_OFF + 128)      // 45776

__device__ __forceinline__ void mma_f16(float* d, const uint32_t* a, uint2 b) {
    asm volatile(
        "mma.sync.aligned.m16n8k16.row.col.f32.f16.f16.f32 "
        "{%0,%1,%2,%3}, {%4,%5,%6,%7}, {%8,%9}, {%0,%1,%2,%3};"
        : "+f"(d[0]), "+f"(d[1]), "+f"(d[2]), "+f"(d[3])
        : "r"(a[0]), "r"(a[1]), "r"(a[2]), "r"(a[3]), "r"(b.x), "r"(b.y));
}

// Weights pre-packed in m16n8k16 B-fragment order, fp16 pairs.
// word index: slab*4608 + (ks*4 + nt)*64 + lane*2 + reg   (ks = t*2 + kc2)
__device__ uint32_t g_w2[41472];

__global__ void prep_w(const float* __restrict__ w) {
    int o = blockIdx.x * 256 + threadIdx.x;
    if (o >= 41472) return;
    int pair = o & 1;             // reg: 0 -> k=2tig, 1 -> k=2tig+8
    int lane = (o >> 1) & 31;
    int nt   = (o >> 6) & 3;
    int ks   = (o >> 8) % 18;
    int slab = o / 4608;
    int tig = lane & 3, gr = lane >> 2;
    int t = ks >> 1, kc2 = ks & 1;
    int ci = kc2 * 16 + tig * 2 + pair * 8;
    int co = nt * 8 + gr;
    int kh = t / 3, kw = t % 3;
    int kl = slab / 3, kd = slab % 3;
    float w0 = w[(ci * 32 + co) * 81 + kl * 27 + kd * 9 + kh * 3 + kw];
    float w1 = w[((ci + 1) * 32 + co) * 81 + kl * 27 + kd * 9 + kh * 3 + kw];
    __half2 hv = __floats2half2_rn(w0, w1);
    g_w2[o] = *(uint32_t*)&hv;
}

__global__ void __launch_bounds__(THREADS, 2)
conv_mma(const float* __restrict__ x, const float* __restrict__ bias,
         float* __restrict__ out)
{
    extern __shared__ char smem[];
    float* bsm = (float*)(smem + BIAS_OFF);

    const int tid  = threadIdx.x;
    const int wid  = tid >> 5;
    const int lane = tid & 31;
    const int gr   = lane >> 2;
    const int tig  = lane & 3;

    if (tid < 32) bsm[tid] = bias[tid];
    // zero xs once: halo cells stay zero; interior overwritten per slab
    for (int i = tid; i < XS_HALFS / 2; i += THREADS) ((uint32_t*)smem)[i] = 0u;

    const int od = blockIdx.x, ol = blockIdx.y;
    const int n  = blockIdx.z >> 1;
    const int h  = blockIdx.z & 1;        // which 12-row output half
    const int hlo = (h == 0) ? 1 : 0;     // first valid hh_l (13 valid rows)
    const int l0 = ol > 0 ? ol - 1 : 0;
    const int l1 = ol < L_ - 1 ? ol + 1 : L_ - 1;
    const int d0 = od > 0 ? od - 1 : 0;
    const int d1 = od < D_ - 1 ? od + 1 : D_ - 1;

    // 2 M-tiles of 16 rows per warp (M = 288 local rows)
    int mb[2], q0b[2], q1b[2];
#pragma unroll
    for (int j = 0; j < 2; j++) {
        mb[j] = (wid * 2 + j) * 16;
        int r0 = mb[j] + gr, r1 = r0 + 8;
        q0b[j] = (r0 / 24) * 27 + (r0 % 24);
        q1b[j] = (r1 / 24) * 27 + (r1 % 24);
    }
    const int dtap[9] = {56, 55, 54, 29, 28, 27, 2, 1, 0};   // (2-kh)*27+(2-kw)

    float d[32];   // [j 2][nt 4][4]
#pragma unroll
    for (int i = 0; i < 32; i++) d[i] = 0.f;

    for (int lp = l0; lp <= l1; lp++) {
        const int kl = ol + 1 - lp;
        for (int dp = d0; dp <= d1; dp++) {
            const int kd = od + 1 - dp;
            __syncthreads();   // previous compute done before overwriting smem

            // ---- stage 13 valid h rows of x plane as fp16 pairs ----
            const float* xsrc = x + ((((size_t)n * 32) * 8 + lp) * 24 + dp) * 576;
            for (int idx = tid; idx < 16 * 13 * 24; idx += THREADS) {
                int iw   = idx % 24;
                int r    = idx / 24;
                int hh_l = r % 13 + hlo;
                int ci2  = r / 13;
                int ih   = h * 12 - 1 + hh_l;
                const float* p = xsrc + (size_t)(2 * ci2) * 110592 + ih * 24 + iw;
                __half2 hv = __floats2half2_rn(p[0], p[110592]);
                *(uint32_t*)(smem + ((hh_l * 27 + iw + 1) * XROW + 2 * ci2) * 2)
                    = *(uint32_t*)&hv;
            }
            // ---- stage fragment-packed B slab ----
            {
                const float4* src = (const float4*)(g_w2 + (kl * 3 + kd) * 4608);
                float4* dst = (float4*)(smem + BS_OFF);
                for (int i = tid; i < 1152; i += THREADS) dst[i] = src[i];
            }
            __syncthreads();

            // ---- compute: 9 taps x 2 k-chunks x (2 mtiles x 4 ntiles) ----
#pragma unroll 1
            for (int t = 0; t < 9; t++) {
                const int dt72 = dtap[t] * 72;
#pragma unroll
                for (int kc2 = 0; kc2 < 2; kc2++) {
                    const int ab = dt72 + kc2 * 32 + tig * 4;
                    uint32_t a[2][4];
#pragma unroll
                    for (int j = 0; j < 2; j++) {
                        const char* b0p = smem + q0b[j] * 72 + ab;
                        const char* b1p = smem + q1b[j] * 72 + ab;
                        a[j][0] = *(const uint32_t*)(b0p);
                        a[j][1] = *(const uint32_t*)(b1p);
                        a[j][2] = *(const uint32_t*)(b0p + 16);
                        a[j][3] = *(const uint32_t*)(b1p + 16);
                    }
                    const int ksb = (t * 2 + kc2) * 4;
#pragma unroll
                    for (int nt = 0; nt < 4; nt++) {
                        uint2 b = *(const uint2*)(smem + BS_OFF
                                   + ((ksb + nt) * 64 + lane * 2) * 4);
                        mma_f16(d + nt * 4,      a[0], b);
                        mma_f16(d + 16 + nt * 4, a[1], b);
                    }
                }
            }
        }
    }

    // ---- epilogue: bias + store ----
    const size_t ob = (((size_t)(n * 32) * 8 + ol) * 24 + od) * 576 + h * 288;
#pragma unroll
    for (int j = 0; j < 2; j++) {
        const int m0 = mb[j] + gr, m1 = m0 + 8;
#pragma unroll
        for (int nt = 0; nt < 4; nt++) {
            const int co0 = nt * 8 + tig * 2;
            const float b0 = bsm[co0], b1 = bsm[co0 + 1];
            const float* dd = d + j * 16 + nt * 4;
            float* o0 = out + ob + (size_t)co0 * 110592;
            float* o1 = o0 + 110592;
            o0[m0] = dd[0] + b0;
            o1[m0] = dd[1] + b1;
            o0[m1] = dd[2] + b0;
            o1[m1] = dd[3] + b1;
        }
    }
}

extern "C" void kernel_launch(void* const* d_in, const int* in_sizes, int n_in,
                              void* d_out, int out_size) {
    const float* x    = (const float*)d_in[0];
    const float* w    = (const float*)d_in[1];
    const float* bias = (const float*)d_in[2];
    float* out = (float*)d_out;

    cudaFuncSetAttribute(conv_mma,
                         cudaFuncAttributeMaxDynamicSharedMemorySize, SMEM_BYTES);

    prep_w<<<162, 256>>>(w);                 // 162*256 == 41472

    dim3 grid(24, L_, 8);                    // (od, ol, n*2 + half)
    conv_mma<<<grid, THREADS, SMEM_BYTES>>>(x, bias, out);
}

// round 7
// speedup vs baseline: 5.1283x; 1.0770x over previous
#include <cuda_runtime.h>
#include <cuda_fp16.h>
#include <cstdint>

// ---------------- problem constants ----------------
#define L_ 8
#define D_ 24
#define THREADS 288

// ---------------- smem layout ----------------
// xs: 378 halo rows (14 hh x 27 ww), each 80 B (32 ci fp16 = 64B + 16B pad)
#define XROW_B 80
#define XS_BYTES (378*XROW_B)            // 30240
#define BS_OFF   XS_BYTES                // B slab: [ks 18][lane 32][12 words]
#define BS_WORDS (18*32*12)              // 6912
#define BIAS_OFF (BS_OFF + BS_WORDS*4)   // 57888
#define SMEM_BYTES (BIAS_OFF + 128)      // 58016

__device__ __forceinline__ void mma_f16(float* d, const uint32_t* a, uint32_t b0, uint32_t b1) {
    asm volatile(
        "mma.sync.aligned.m16n8k16.row.col.f32.f16.f16.f32 "
        "{%0,%1,%2,%3}, {%4,%5,%6,%7}, {%8,%9}, {%0,%1,%2,%3};"
        : "+f"(d[0]), "+f"(d[1]), "+f"(d[2]), "+f"(d[3])
        : "r"(a[0]), "r"(a[1]), "r"(a[2]), "r"(a[3]), "r"(b0), "r"(b1));
}
__device__ __forceinline__ void ldsm_x4(uint32_t* a, uint32_t addr) {
    asm volatile("ldmatrix.sync.aligned.m8n8.x4.shared.b16 {%0,%1,%2,%3}, [%4];"
                 : "=r"(a[0]), "=r"(a[1]), "=r"(a[2]), "=r"(a[3]) : "r"(addr));
}
__device__ __forceinline__ uint32_t smem_u32(const void* p) {
    uint32_t a;
    asm("{ .reg .u64 t; cvta.to.shared.u64 t, %1; cvt.u32.u64 %0, t; }" : "=r"(a) : "l"(p));
    return a;
}

// Weights: [slab 9][ks 18][lane 32][12 words], words 0-7 = nt*2+reg, 8-11 pad
__device__ uint32_t g_w2[9*6912];

__global__ void prep_w(const float* __restrict__ w) {
    int o = blockIdx.x * 256 + threadIdx.x;
    if (o >= 9*6912) return;
    int slab = o / 6912;
    int rem  = o % 6912;
    int ks   = rem / 384;
    int lane = (rem % 384) / 12;
    int wd   = rem % 12;
    if (wd >= 8) { g_w2[o] = 0u; return; }
    int nt = wd >> 1, pair = wd & 1;
    int tig = lane & 3, gr = lane >> 2;
    int t = ks >> 1, kc2 = ks & 1;
    int ci = kc2 * 16 + tig * 2 + pair * 8;
    int co = nt * 8 + gr;
    int kh = t / 3, kw = t % 3;
    int kl = slab / 3, kd = slab % 3;
    float w0 = w[(ci * 32 + co) * 81 + kl * 27 + kd * 9 + kh * 3 + kw];
    float w1 = w[((ci + 1) * 32 + co) * 81 + kl * 27 + kd * 9 + kh * 3 + kw];
    __half2 hv = __floats2half2_rn(w0, w1);
    g_w2[o] = *(uint32_t*)&hv;
}

__global__ void __launch_bounds__(THREADS, 2)
conv_mma(const float* __restrict__ x, const float* __restrict__ bias,
         float* __restrict__ out)
{
    extern __shared__ char smem[];
    float* bsm = (float*)(smem + BIAS_OFF);
    const uint32_t sb = smem_u32(smem);

    const int tid  = threadIdx.x;
    const int wid  = tid >> 5;
    const int lane = tid & 31;
    const int gr   = lane >> 2;
    const int tig  = lane & 3;

    if (tid < 32) bsm[tid] = bias[tid];
    // zero xs once: halo cells stay zero; interior overwritten per slab
    for (int i = tid; i < XS_BYTES / 4; i += THREADS) ((uint32_t*)smem)[i] = 0u;

    const int od = blockIdx.x, ol = blockIdx.y;
    const int n  = blockIdx.z >> 1;
    const int h  = blockIdx.z & 1;        // which 12-row output half
    const int hlo = (h == 0) ? 1 : 0;     // first valid hh_l (13 valid rows)
    const int l0 = ol > 0 ? ol - 1 : 0;
    const int l1 = ol < L_ - 1 ? ol + 1 : L_ - 1;
    const int d0 = od > 0 ? od - 1 : 0;
    const int d1 = od < D_ - 1 ? od + 1 : D_ - 1;

    // 2 M-tiles of 16 rows per warp; ldmatrix per-lane base addresses
    int mb[2];
    uint32_t qa[2];
#pragma unroll
    for (int j = 0; j < 2; j++) {
        mb[j] = (wid * 2 + j) * 16;
        int r = mb[j] + (lane & 7) + ((lane >> 3) & 1) * 8;  // lane's matrix row
        int q = (r / 24) * 27 + (r % 24);                     // halo coords
        qa[j] = sb + q * XROW_B + ((lane >> 4) & 1) * 16;     // + ci-half chunk
    }
    const int dtap[9] = {56, 55, 54, 29, 28, 27, 2, 1, 0};   // (2-kh)*27+(2-kw)

    float d[32];   // [j 2][nt 4][4]
#pragma unroll
    for (int i = 0; i < 32; i++) d[i] = 0.f;

    for (int lp = l0; lp <= l1; lp++) {
        const int kl = ol + 1 - lp;
        for (int dp = d0; dp <= d1; dp++) {
            const int kd = od + 1 - dp;
            __syncthreads();   // previous compute done before overwriting smem

            // ---- stage 13 valid h rows of x plane as fp16 pairs ----
            const float* xsrc = x + ((((size_t)n * 32) * 8 + lp) * 24 + dp) * 576;
            for (int idx = tid; idx < 16 * 13 * 24; idx += THREADS) {
                int iw   = idx % 24;
                int r    = idx / 24;
                int hh_l = r % 13 + hlo;
                int ci2  = r / 13;
                int ih   = h * 12 - 1 + hh_l;
                const float* p = xsrc + (size_t)(2 * ci2) * 110592 + ih * 24 + iw;
                __half2 hv = __floats2half2_rn(p[0], p[110592]);
                *(uint32_t*)(smem + (hh_l * 27 + iw + 1) * XROW_B + 4 * ci2)
                    = *(uint32_t*)&hv;
            }
            // ---- stage B slab (27648 B) ----
            {
                const float4* src = (const float4*)(g_w2 + (kl * 3 + kd) * 6912);
                float4* dst = (float4*)(smem + BS_OFF);
                for (int i = tid; i < 1728; i += THREADS) dst[i] = src[i];
            }
            __syncthreads();

            // ---- compute: 9 taps x 2 kc2 x (2 LDSM + 2 LDS.128 + 8 MMA) ----
#pragma unroll 1
            for (int t = 0; t < 9; t++) {
                const int dt80 = dtap[t] * XROW_B;
#pragma unroll
                for (int kc2 = 0; kc2 < 2; kc2++) {
                    uint32_t a0[4], a1[4];
                    ldsm_x4(a0, qa[0] + dt80 + kc2 * 32);
                    ldsm_x4(a1, qa[1] + dt80 + kc2 * 32);
                    const uint4* bq = (const uint4*)(smem + BS_OFF
                                      + ((t * 2 + kc2) * 32 + lane) * 48);
                    uint4 v0 = bq[0], v1 = bq[1];
                    mma_f16(d + 0,  a0, v0.x, v0.y);
                    mma_f16(d + 16, a1, v0.x, v0.y);
                    mma_f16(d + 4,  a0, v0.z, v0.w);
                    mma_f16(d + 20, a1, v0.z, v0.w);
                    mma_f16(d + 8,  a0, v1.x, v1.y);
                    mma_f16(d + 24, a1, v1.x, v1.y);
                    mma_f16(d + 12, a0, v1.z, v1.w);
                    mma_f16(d + 28, a1, v1.z, v1.w);
                }
            }
        }
    }

    // ---- epilogue: bias + store ----
    const size_t ob = (((size_t)(n * 32) * 8 + ol) * 24 + od) * 576 + h * 288;
#pragma unroll
    for (int j = 0; j < 2; j++) {
        const int m0 = mb[j] + gr, m1 = m0 + 8;
#pragma unroll
        for (int nt = 0; nt < 4; nt++) {
            const int co0 = nt * 8 + tig * 2;
            const float b0 = bsm[co0], b1 = bsm[co0 + 1];
            const float* dd = d + j * 16 + nt * 4;
            float* o0 = out + ob + (size_t)co0 * 110592;
            float* o1 = o0 + 110592;
            o0[m0] = dd[0] + b0;
            o1[m0] = dd[1] + b1;
            o0[m1] = dd[2] + b0;
            o1[m1] = dd[3] + b1;
        }
    }
}

extern "C" void kernel_launch(void* const* d_in, const int* in_sizes, int n_in,
                              void* d_out, int out_size) {
    const float* x    = (const float*)d_in[0];
    const float* w    = (const float*)d_in[1];
    const float* bias = (const float*)d_in[2];
    float* out = (float*)d_out;

    cudaFuncSetAttribute(conv_mma,
                         cudaFuncAttributeMaxDynamicSharedMemorySize, SMEM_BYTES);

    prep_w<<<243, 256>>>(w);                 // 243*256 == 62208

    dim3 grid(24, L_, 8);                    // (od, ol, n*2 + half)
    conv_mma<<<grid, THREADS, SMEM_BYTES>>>(x, bias, out);
}

// round 8
// speedup vs baseline: 6.5107x; 1.2696x over previous
#include <cuda_runtime.h>
#include <cuda_fp16.h>
#include <cstdint>

// ---------------- problem constants ----------------
#define L_ 8
#define D_ 24
#define THREADS 288

// ---------------- smem layout (per buffer) ----------------
#define XROW_B 80                 // 32 ci fp16 (64B) + 16B pad (bank-safe, 16B aligned)
#define XS_SZ  30160              // 377 rows x 80 B (row 377 never read)
#define BS_SZ  27632              // 1727 x 16B (18 ks x 32 lane x 12 words, last pad chunk dropped)
#define BUFSTRIDE (XS_SZ + BS_SZ) // 57792
#define SMEM_BYTES (2*BUFSTRIDE)  // 115584  (2 CTAs/SM: 2*(115584+1024) = 233216 <= 233472)

__device__ __forceinline__ void mma_f16(float* d, const uint32_t* a, uint32_t b0, uint32_t b1) {
    asm volatile(
        "mma.sync.aligned.m16n8k16.row.col.f32.f16.f16.f32 "
        "{%0,%1,%2,%3}, {%4,%5,%6,%7}, {%8,%9}, {%0,%1,%2,%3};"
        : "+f"(d[0]), "+f"(d[1]), "+f"(d[2]), "+f"(d[3])
        : "r"(a[0]), "r"(a[1]), "r"(a[2]), "r"(a[3]), "r"(b0), "r"(b1));
}
__device__ __forceinline__ void ldsm_x4(uint32_t* a, uint32_t addr) {
    asm volatile("ldmatrix.sync.aligned.m8n8.x4.shared.b16 {%0,%1,%2,%3}, [%4];"
                 : "=r"(a[0]), "=r"(a[1]), "=r"(a[2]), "=r"(a[3]) : "r"(addr));
}
__device__ __forceinline__ uint32_t smem_u32(const void* p) {
    uint32_t a;
    asm("{ .reg .u64 t; cvta.to.shared.u64 t, %1; cvt.u32.u64 %0, t; }" : "=r"(a) : "l"(p));
    return a;
}
__device__ __forceinline__ void cpa16(uint32_t dst, const void* src) {
    asm volatile("cp.async.cg.shared.global [%0], [%1], 16;" :: "r"(dst), "l"(src) : "memory");
}
__device__ __forceinline__ void cpa_commit() {
    asm volatile("cp.async.commit_group;" ::: "memory");
}

// ---------------- device globals ----------------
// x transposed to [n][l][d][h][w][ci] fp16
__device__ __half g_xh[4*8*24*24*24*32];
// weights fragment-packed: [slab 9][ks 18][lane 32][12 words] (words 8-11 pad)
__device__ uint32_t g_w2[9*6912];

__global__ void prep_w(const float* __restrict__ w) {
    int o = blockIdx.x * 256 + threadIdx.x;
    if (o >= 9*6912) return;
    int slab = o / 6912;
    int rem  = o % 6912;
    int ks   = rem / 384;
    int lane = (rem % 384) / 12;
    int wd   = rem % 12;
    if (wd >= 8) { g_w2[o] = 0u; return; }
    int nt = wd >> 1, pair = wd & 1;
    int tig = lane & 3, gr = lane >> 2;
    int t = ks >> 1, kc2 = ks & 1;
    int ci = kc2 * 16 + tig * 2 + pair * 8;
    int co = nt * 8 + gr;
    int kh = t / 3, kw = t % 3;
    int kl = slab / 3, kd = slab % 3;
    float w0 = w[(ci * 32 + co) * 81 + kl * 27 + kd * 9 + kh * 3 + kw];
    float w1 = w[((ci + 1) * 32 + co) * 81 + kl * 27 + kd * 9 + kh * 3 + kw];
    __half2 hv = __floats2half2_rn(w0, w1);
    g_w2[o] = *(uint32_t*)&hv;
}

// transpose one (n,l,d) plane: [ci][hw] fp32 -> [hw][ci] fp16 (both sides coalesced)
__global__ void __launch_bounds__(576, 2)
prep_x(const float* __restrict__ x) {
    __shared__ uint32_t sx[576*16];
    int plane = blockIdx.x;                  // (n*8+l)*24+d
    int t = threadIdx.x;                     // hw
    int n = plane / 192, l = (plane / 24) % 8, d = plane % 24;
    const float* base = x + (((size_t)(n*32)*8 + l)*24 + d)*576 + t;
#pragma unroll
    for (int ci2 = 0; ci2 < 16; ci2++) {
        float v0 = base[(size_t)(2*ci2)   * 110592];
        float v1 = base[(size_t)(2*ci2+1) * 110592];
        __half2 hv = __floats2half2_rn(v0, v1);
        sx[t*16 + ci2] = *(uint32_t*)&hv;
    }
    __syncthreads();
    uint32_t* gw = (uint32_t*)g_xh + (size_t)plane * 9216;
#pragma unroll
    for (int k = 0; k < 16; k++) gw[k*576 + t] = sx[k*576 + t];
}

__global__ void __launch_bounds__(THREADS, 2)
conv_mma(const float* __restrict__ bias, float* __restrict__ out)
{
    extern __shared__ char smem[];
    const uint32_t sb = smem_u32(smem);

    const int tid  = threadIdx.x;
    const int wid  = tid >> 5;
    const int lane = tid & 31;
    const int gr   = lane >> 2;
    const int tig  = lane & 3;

    const int od = blockIdx.x, ol = blockIdx.y;
    const int n  = blockIdx.z >> 1;
    const int h  = blockIdx.z & 1;        // 12-row output half
    const int hlo = (h == 0) ? 1 : 0;
    const int l0 = ol > 0 ? ol - 1 : 0;
    const int l1 = ol < L_ - 1 ? ol + 1 : L_ - 1;
    const int d0 = od > 0 ? od - 1 : 0;
    const int d1 = od < D_ - 1 ? od + 1 : D_ - 1;
    const int nd = d1 - d0 + 1;
    const int ns = (l1 - l0 + 1) * nd;

    // zero XS halo regions of both buffers (staging writes only interior rows)
    for (int i = tid; i < (2*XS_SZ)/4; i += THREADS) {
        int b = (i < XS_SZ/4) ? 0 : 1;
        int w = (b == 0) ? i : i - XS_SZ/4;
        *(uint32_t*)(smem + b*BUFSTRIDE + w*4) = 0u;
    }

    // ldmatrix per-lane base addresses (2 M-tiles of 16 rows per warp)
    int mb[2];
    uint32_t qa[2];
#pragma unroll
    for (int j = 0; j < 2; j++) {
        mb[j] = (wid * 2 + j) * 16;
        int r = mb[j] + (lane & 7) + ((lane >> 3) & 1) * 8;
        int q = (r / 24) * 27 + (r % 24);
        qa[j] = sb + q * XROW_B + ((lane >> 4) & 1) * 16;
    }
    const int dtap[9] = {56, 55, 54, 29, 28, 27, 2, 1, 0};   // (2-kh)*27+(2-kw)

    float d[32];
#pragma unroll
    for (int i = 0; i < 32; i++) d[i] = 0.f;

    // ---- staging as cp.async (pre-transposed fp16 x + prepacked B) ----
    auto stage = [&](int s, int buf) {
        int lp = l0 + s / nd;
        int dp = d0 + s % nd;
        int kl = ol + 1 - lp, kd = od + 1 - dp;
        const __half* xsrc = g_xh + (size_t)(((n*8 + lp)*24 + dp)) * 576 * 32;
        uint32_t xb = sb + buf * BUFSTRIDE;
        for (int idx = tid; idx < 1248; idx += THREADS) {
            int ch = idx & 3;
            int r  = idx >> 2;              // 0..311
            int iw = r % 24;
            int hh_l = r / 24 + hlo;        // 13 valid rows
            int ih = h * 12 - 1 + hh_l;
            cpa16(xb + (hh_l * 27 + iw + 1) * XROW_B + ch * 16,
                  xsrc + (ih * 24 + iw) * 32 + ch * 8);
        }
        const char* bsrc = (const char*)(g_w2 + (kl * 3 + kd) * 6912);
        uint32_t bb = sb + buf * BUFSTRIDE + XS_SZ;
        for (int i = tid; i < 1727; i += THREADS)
            cpa16(bb + i * 16, bsrc + (size_t)i * 16);
    };

    __syncthreads();                 // zero-fill visible before first compute
    stage(0, 0); cpa_commit();
    if (ns > 1) stage(1, 1);
    cpa_commit();

    for (int s = 0; s < ns; s++) {
        if (s + 1 < ns) asm volatile("cp.async.wait_group 1;" ::: "memory");
        else            asm volatile("cp.async.wait_group 0;" ::: "memory");
        __syncthreads();

        const uint32_t bufoff = (s & 1) * BUFSTRIDE;
        const uint32_t qa0 = qa[0] + bufoff, qa1 = qa[1] + bufoff;
        const char* bsl = smem + bufoff + XS_SZ;

#pragma unroll 3
        for (int t = 0; t < 9; t++) {
            const int dt80 = dtap[t] * XROW_B;
#pragma unroll
            for (int kc2 = 0; kc2 < 2; kc2++) {
                uint32_t a0[4], a1[4];
                ldsm_x4(a0, qa0 + dt80 + kc2 * 32);
                ldsm_x4(a1, qa1 + dt80 + kc2 * 32);
                const uint4* bq = (const uint4*)(bsl + ((t * 2 + kc2) * 32 + lane) * 48);
                uint4 v0 = bq[0], v1 = bq[1];
                mma_f16(d + 0,  a0, v0.x, v0.y);
                mma_f16(d + 16, a1, v0.x, v0.y);
                mma_f16(d + 4,  a0, v0.z, v0.w);
                mma_f16(d + 20, a1, v0.z, v0.w);
                mma_f16(d + 8,  a0, v1.x, v1.y);
                mma_f16(d + 24, a1, v1.x, v1.y);
                mma_f16(d + 12, a0, v1.z, v1.w);
                mma_f16(d + 28, a1, v1.z, v1.w);
            }
        }
        __syncthreads();             // compute done before buffer is restaged
        if (s + 2 < ns) stage(s + 2, s & 1);
        cpa_commit();
    }

    // ---- epilogue: bias + store ----
    const size_t ob = (((size_t)(n * 32) * 8 + ol) * 24 + od) * 576 + h * 288;
#pragma unroll
    for (int j = 0; j < 2; j++) {
        const int m0 = mb[j] + gr, m1 = m0 + 8;
#pragma unroll
        for (int nt = 0; nt < 4; nt++) {
            const int co0 = nt * 8 + tig * 2;
            const float b0 = __ldg(bias + co0);
            const float b1 = __ldg(bias + co0 + 1);
            const float* dd = d + j * 16 + nt * 4;
            float* o0 = out + ob + (size_t)co0 * 110592;
            float* o1 = o0 + 110592;
            o0[m0] = dd[0] + b0;
            o1[m0] = dd[1] + b1;
            o0[m1] = dd[2] + b0;
            o1[m1] = dd[3] + b1;
        }
    }
}

extern "C" void kernel_launch(void* const* d_in, const int* in_sizes, int n_in,
                              void* d_out, int out_size) {
    const float* x    = (const float*)d_in[0];
    const float* w    = (const float*)d_in[1];
    const float* bias = (const float*)d_in[2];
    float* out = (float*)d_out;

    cudaFuncSetAttribute(conv_mma,
                         cudaFuncAttributeMaxDynamicSharedMemorySize, SMEM_BYTES);

    prep_w<<<243, 256>>>(w);                 // 243*256 == 62208
    prep_x<<<768, 576>>>(x);                 // one block per (n,l,d) plane

    dim3 grid(24, L_, 8);                    // (od, ol, n*2 + half)
    conv_mma<<<grid, THREADS, SMEM_BYTES>>>(bias, out);
}

// round 10
// speedup vs baseline: 7.8571x; 1.2068x over previous
#include <cuda_runtime.h>
#include <cuda_fp16.h>
#include <cstdint>

// ---------------- problem constants ----------------
#define L_ 8
#define D_ 24
#define THREADS 320              // 9 compute warps + 1 producer warp

// ---------------- smem layout (per buffer) ----------------
#define XROW_B 80                 // 32 ci fp16 (64B) + 16B pad (bank-safe, 16B aligned)
#define XS_SZ  30160              // 377 rows x 80 B
#define BS_SZ  27632              // 1727 x 16B
#define BUFSTRIDE (XS_SZ + BS_SZ) // 57792
#define MB_OFF (2*BUFSTRIDE)      // mbarriers: full0,full1,empty0,empty1 (8B each)
#define SMEM_BYTES (MB_OFF + 64)  // 115648; 2 CTAs: 2*(115648+1024)=233344 <= 233472

__device__ __forceinline__ void mma_f16(float* d, const uint32_t* a, uint32_t b0, uint32_t b1) {
    asm volatile(
        "mma.sync.aligned.m16n8k16.row.col.f32.f16.f16.f32 "
        "{%0,%1,%2,%3}, {%4,%5,%6,%7}, {%8,%9}, {%0,%1,%2,%3};"
        : "+f"(d[0]), "+f"(d[1]), "+f"(d[2]), "+f"(d[3])
        : "r"(a[0]), "r"(a[1]), "r"(a[2]), "r"(a[3]), "r"(b0), "r"(b1));
}
__device__ __forceinline__ void ldsm_x4(uint32_t* a, uint32_t addr) {
    asm volatile("ldmatrix.sync.aligned.m8n8.x4.shared.b16 {%0,%1,%2,%3}, [%4];"
                 : "=r"(a[0]), "=r"(a[1]), "=r"(a[2]), "=r"(a[3]) : "r"(addr));
}
__device__ __forceinline__ uint32_t smem_u32(const void* p) {
    uint32_t a;
    asm("{ .reg .u64 t; cvta.to.shared.u64 t, %1; cvt.u32.u64 %0, t; }" : "=r"(a) : "l"(p));
    return a;
}
__device__ __forceinline__ void cpa16(uint32_t dst, const void* src) {
    asm volatile("cp.async.cg.shared.global [%0], [%1], 16;" :: "r"(dst), "l"(src) : "memory");
}
__device__ __forceinline__ void mbar_wait(uint32_t mbar, uint32_t par) {
    asm volatile(
        "{\n\t.reg .pred P;\n\tWL%=:\n\t"
        "mbarrier.try_wait.parity.shared.b64 P, [%0], %1;\n\t"
        "@P bra.uni WD%=;\n\tbra.uni WL%=;\n\tWD%=:\n\t}"
        :: "r"(mbar), "r"(par) : "memory");
}
__device__ __forceinline__ void mbar_arrive(uint32_t mbar) {
    asm volatile("{\n\t.reg .b64 t;\n\tmbarrier.arrive.shared.b64 t, [%0];\n\t}"
                 :: "r"(mbar) : "memory");
}

// ---------------- device globals ----------------
__device__ __half g_xh[4*8*24*24*24*32];         // x as [n][l][d][h][w][ci] fp16
__device__ uint32_t g_w2[9*6912];                // [slab][ks 18][lane 32][12 words]

__global__ void prep_w(const float* __restrict__ w) {
    int o = blockIdx.x * 256 + threadIdx.x;
    if (o >= 9*6912) return;
    int slab = o / 6912;
    int rem  = o % 6912;
    int ks   = rem / 384;
    int lane = (rem % 384) / 12;
    int wd   = rem % 12;
    if (wd >= 8) { g_w2[o] = 0u; return; }
    int nt = wd >> 1, pair = wd & 1;
    int tig = lane & 3, gr = lane >> 2;
    int t = ks >> 1, kc2 = ks & 1;
    int ci = kc2 * 16 + tig * 2 + pair * 8;
    int co = nt * 8 + gr;
    int kh = t / 3, kw = t % 3;
    int kl = slab / 3, kd = slab % 3;
    float w0 = w[(ci * 32 + co) * 81 + kl * 27 + kd * 9 + kh * 3 + kw];
    float w1 = w[((ci + 1) * 32 + co) * 81 + kl * 27 + kd * 9 + kh * 3 + kw];
    __half2 hv = __floats2half2_rn(w0, w1);
    g_w2[o] = *(uint32_t*)&hv;
}

__global__ void __launch_bounds__(576, 2)
prep_x(const float* __restrict__ x) {
    __shared__ uint32_t sx[576*16];
    int plane = blockIdx.x;                  // (n*8+l)*24+d
    int t = threadIdx.x;                     // hw
    int n = plane / 192, l = (plane / 24) % 8, d = plane % 24;
    const float* base = x + (((size_t)(n*32)*8 + l)*24 + d)*576 + t;
#pragma unroll
    for (int ci2 = 0; ci2 < 16; ci2++) {
        float v0 = base[(size_t)(2*ci2)   * 110592];
        float v1 = base[(size_t)(2*ci2+1) * 110592];
        __half2 hv = __floats2half2_rn(v0, v1);
        sx[t*16 + ci2] = *(uint32_t*)&hv;
    }
    __syncthreads();
    uint32_t* gw = (uint32_t*)g_xh + (size_t)plane * 9216;
#pragma unroll
    for (int k = 0; k < 16; k++) gw[k*576 + t] = sx[k*576 + t];
}

__global__ void __launch_bounds__(THREADS, 2)
conv_mma(const float* __restrict__ bias, float* __restrict__ out)
{
    extern __shared__ char smem[];
    const uint32_t sb = smem_u32(smem);

    const int tid  = threadIdx.x;
    const int wid  = tid >> 5;
    const int lane = tid & 31;
    const int gr   = lane >> 2;
    const int tig  = lane & 3;

    const int od = blockIdx.x, ol = blockIdx.y;
    const int n  = blockIdx.z >> 1;
    const int h  = blockIdx.z & 1;        // 12-row output half
    const int hlo = (h == 0) ? 1 : 0;
    const int l0 = ol > 0 ? ol - 1 : 0;
    const int l1 = ol < L_ - 1 ? ol + 1 : L_ - 1;
    const int d0 = od > 0 ? od - 1 : 0;
    const int d1 = od < D_ - 1 ? od + 1 : D_ - 1;
    const int nd = d1 - d0 + 1;
    const int ns = (l1 - l0 + 1) * nd;

    const uint32_t mb_full0  = sb + MB_OFF;
    const uint32_t mb_full1  = sb + MB_OFF + 8;
    const uint32_t mb_empty0 = sb + MB_OFF + 16;
    const uint32_t mb_empty1 = sb + MB_OFF + 24;

    if (tid == 0) {
        asm volatile("mbarrier.init.shared.b64 [%0], 32;" :: "r"(mb_full0) : "memory");
        asm volatile("mbarrier.init.shared.b64 [%0], 32;" :: "r"(mb_full1) : "memory");
        asm volatile("mbarrier.init.shared.b64 [%0], 9;"  :: "r"(mb_empty0) : "memory");
        asm volatile("mbarrier.init.shared.b64 [%0], 9;"  :: "r"(mb_empty1) : "memory");
    }

    // zero XS halo regions of both buffers (producer writes only interior rows)
    for (int i = tid; i < (2*XS_SZ)/4; i += THREADS) {
        int b = (i < XS_SZ/4) ? 0 : 1;
        int w = (b == 0) ? i : i - XS_SZ/4;
        *(uint32_t*)(smem + b*BUFSTRIDE + w*4) = 0u;
    }
    __syncthreads();   // mbarriers + zero-fill visible; last block-wide sync

    if (wid == 9) {
        // ================= producer warp =================
        int eph0 = 0, eph1 = 0;
        for (int s = 0; s < ns; s++) {
            const int buf = s & 1;
            if (s >= 2) {
                if (buf == 0) { mbar_wait(mb_empty0, eph0); eph0 ^= 1; }
                else          { mbar_wait(mb_empty1, eph1); eph1 ^= 1; }
            }
            const int lp = l0 + s / nd;
            const int dp = d0 + s % nd;
            const int kl = ol + 1 - lp, kd = od + 1 - dp;
            const __half* xsrc = g_xh + (size_t)(((n*8 + lp)*24 + dp)) * 576 * 32;
            const uint32_t xb = sb + buf * BUFSTRIDE;
            for (int idx = lane; idx < 1248; idx += 32) {
                int ch = idx & 3;
                int r  = idx >> 2;              // 0..311
                int iw = r % 24;
                int hh_l = r / 24 + hlo;        // 13 valid rows
                int ih = h * 12 - 1 + hh_l;
                cpa16(xb + (hh_l * 27 + iw + 1) * XROW_B + ch * 16,
                      xsrc + (ih * 24 + iw) * 32 + ch * 8);
            }
            const char* bsrc = (const char*)(g_w2 + (kl * 3 + kd) * 6912);
            const uint32_t bb = xb + XS_SZ;
            for (int i = lane; i < 1727; i += 32)
                cpa16(bb + i * 16, bsrc + (size_t)i * 16);
            // completion of this lane's prior cp.asyncs -> ONE counted arrival
            // (.noinc: counts against the init count of 32, no pending increment)
            asm volatile("cp.async.mbarrier.arrive.noinc.shared.b64 [%0];"
                         :: "r"(buf == 0 ? mb_full0 : mb_full1) : "memory");
        }
        return;
    }

    // ================= consumer warps (wid 0..8) =================
    int mb[2];
    uint32_t qa[2];
#pragma unroll
    for (int j = 0; j < 2; j++) {
        mb[j] = (wid * 2 + j) * 16;
        int r = mb[j] + (lane & 7) + ((lane >> 3) & 1) * 8;
        int q = (r / 24) * 27 + (r % 24);
        qa[j] = sb + q * XROW_B + ((lane >> 4) & 1) * 16;
    }
    const int dtap[9] = {56, 55, 54, 29, 28, 27, 2, 1, 0};   // (2-kh)*27+(2-kw)

    float d[32];
#pragma unroll
    for (int i = 0; i < 32; i++) d[i] = 0.f;

    int fph0 = 0, fph1 = 0;
    for (int s = 0; s < ns; s++) {
        const int buf = s & 1;
        if (buf == 0) { mbar_wait(mb_full0, fph0); fph0 ^= 1; }
        else          { mbar_wait(mb_full1, fph1); fph1 ^= 1; }

        const uint32_t bufoff = buf * BUFSTRIDE;
        const uint32_t qa0 = qa[0] + bufoff, qa1 = qa[1] + bufoff;
        const char* bsl = smem + bufoff + XS_SZ;

#pragma unroll 3
        for (int t = 0; t < 9; t++) {
            const int dt80 = dtap[t] * XROW_B;
#pragma unroll
            for (int kc2 = 0; kc2 < 2; kc2++) {
                uint32_t a0[4], a1[4];
                ldsm_x4(a0, qa0 + dt80 + kc2 * 32);
                ldsm_x4(a1, qa1 + dt80 + kc2 * 32);
                const uint4* bq = (const uint4*)(bsl + ((t * 2 + kc2) * 32 + lane) * 48);
                uint4 v0 = bq[0], v1 = bq[1];
                mma_f16(d + 0,  a0, v0.x, v0.y);
                mma_f16(d + 16, a1, v0.x, v0.y);
                mma_f16(d + 4,  a0, v0.z, v0.w);
                mma_f16(d + 20, a1, v0.z, v0.w);
                mma_f16(d + 8,  a0, v1.x, v1.y);
                mma_f16(d + 24, a1, v1.x, v1.y);
                mma_f16(d + 12, a0, v1.z, v1.w);
                mma_f16(d + 28, a1, v1.z, v1.w);
            }
        }
        if (lane == 0) mbar_arrive(buf == 0 ? mb_empty0 : mb_empty1);
    }

    // ---- epilogue: bias + store ----
    const size_t ob = (((size_t)(n * 32) * 8 + ol) * 24 + od) * 576 + h * 288;
#pragma unroll
    for (int j = 0; j < 2; j++) {
        const int m0 = mb[j] + gr, m1 = m0 + 8;
#pragma unroll
        for (int nt = 0; nt < 4; nt++) {
            const int co0 = nt * 8 + tig * 2;
            const float b0 = __ldg(bias + co0);
            const float b1 = __ldg(bias + co0 + 1);
            const float* dd = d + j * 16 + nt * 4;
            float* o0 = out + ob + (size_t)co0 * 110592;
            float* o1 = o0 + 110592;
            o0[m0] = dd[0] + b0;
            o1[m0] = dd[1] + b1;
            o0[m1] = dd[2] + b0;
            o1[m1] = dd[3] + b1;
        }
    }
}

extern "C" void kernel_launch(void* const* d_in, const int* in_sizes, int n_in,
                              void* d_out, int out_size) {
    const float* x    = (const float*)d_in[0];
    const float* w    = (const float*)d_in[1];
    const float* bias = (const float*)d_in[2];
    float* out = (float*)d_out;

    cudaFuncSetAttribute(conv_mma,
                         cudaFuncAttributeMaxDynamicSharedMemorySize, SMEM_BYTES);

    prep_w<<<243, 256>>>(w);                 // 243*256 == 62208
    prep_x<<<768, 576>>>(x);                 // one block per (n,l,d) plane

    dim3 grid(24, L_, 8);                    // (od, ol, n*2 + half)
    conv_mma<<<grid, THREADS, SMEM_BYTES>>>(bias, out);
}